// round 16
// baseline (speedup 1.0000x reference)
#include <cuda_runtime.h>
#include <cuda_bf16.h>
#include <math.h>
#include <stdint.h>

#define N_NODES  20000
#define N_FEAT   128
#define HEADS    56
#define OUTD     32
#define D1       1792      // HEADS*OUTD
#define N_EDGES  100000
#define E_TOT    120000    // + self loops
#define N_GRAPHS 50
#define N_CLASS  2
#define EPS_BN   1e-5f

// ---------------- scratch (static device memory; no allocations) ------------
__device__ __nv_bfloat16 g_hbf [(size_t)N_NODES * D1];   // bf16 h (per layer)
__device__ __nv_bfloat16 g_actbf[(size_t)N_NODES * D1];  // bf16 activations
__device__ __nv_bfloat16 g_xbf [(size_t)N_NODES * N_FEAT];
__device__ __nv_bfloat16 g_w1t [(size_t)D1 * N_FEAT];    // W1^T [N][K]
__device__ __nv_bfloat16 g_w2t [(size_t)D1 * D1];        // W2^T [N][K]
__device__ float g_as[N_NODES * HEADS];
__device__ float g_ad[N_NODES * HEADS];
__device__ int   g_deg[N_NODES];
__device__ int   g_rowptr[N_NODES + 1];
__device__ int   g_next[N_NODES];
__device__ int   g_csr[E_TOT];          // src per CSR slot (by dst)
__device__ float g_pool[N_GRAPHS * OUTD];
__device__ float g_cnt[N_GRAPHS];

// ---------------- helpers ---------------------------------------------------
// .cg: bypass L1 allocation for staged tiles (single-use data; B reuse is in L2)
__device__ __forceinline__ void cpAsync16(uint32_t smem_addr, const void* gptr, int src_bytes) {
    asm volatile("cp.async.cg.shared.global [%0], [%1], 16, %2;"
                 :: "r"(smem_addr), "l"(gptr), "r"(src_bytes));
}
__device__ __forceinline__ void cpCommit() { asm volatile("cp.async.commit_group;"); }
template <int N>
__device__ __forceinline__ void cpWait() { asm volatile("cp.async.wait_group %0;" :: "n"(N)); }

__device__ __forceinline__ void ldsmX4(uint32_t& r0, uint32_t& r1, uint32_t& r2, uint32_t& r3,
                                       uint32_t addr) {
    asm volatile("ldmatrix.sync.aligned.m8n8.x4.shared.b16 {%0,%1,%2,%3}, [%4];"
                 : "=r"(r0), "=r"(r1), "=r"(r2), "=r"(r3) : "r"(addr));
}

__device__ __forceinline__ void edge_sd(const int* __restrict__ ei, int e, int& s, int& d) {
    if (e < N_EDGES) { s = ei[e]; d = ei[N_EDGES + e]; }
    else             { s = d = e - N_EDGES; }
}

// ---------------- f32 -> bf16 elementwise (vector of 4) ---------------------
__global__ void cvt_bf16(const float* __restrict__ in, __nv_bfloat16* __restrict__ out, int n4) {
    int i = blockIdx.x * blockDim.x + threadIdx.x;
    if (i >= n4) return;
    float4 v = ((const float4*)in)[i];
    ((__nv_bfloat162*)out)[2 * i]     = __floats2bfloat162_rn(v.x, v.y);
    ((__nv_bfloat162*)out)[2 * i + 1] = __floats2bfloat162_rn(v.z, v.w);
}

// ---------------- f32 [K][N] -> bf16 [N][K] tiled transpose -----------------
__global__ void transpose_cvt(const float* __restrict__ in, __nv_bfloat16* __restrict__ out,
                              int K, int N) {
    __shared__ float tile[32][33];
    int k0 = blockIdx.y * 32, n0 = blockIdx.x * 32;
    #pragma unroll
    for (int j = 0; j < 4; j++) {
        int kk = threadIdx.y + j * 8;
        tile[kk][threadIdx.x] = in[(size_t)(k0 + kk) * N + n0 + threadIdx.x];
    }
    __syncthreads();
    #pragma unroll
    for (int j = 0; j < 4; j++) {
        int nn = threadIdx.y + j * 8;
        out[(size_t)(n0 + nn) * K + k0 + threadIdx.x] = __float2bfloat16(tile[threadIdx.x][nn]);
    }
}

// ---------------- CSR build --------------------------------------------------
__global__ void count_deg(const int* __restrict__ ei) {
    int e = blockIdx.x * blockDim.x + threadIdx.x;
    if (e >= E_TOT) return;
    int s, d; edge_sd(ei, e, s, d);
    atomicAdd(&g_deg[d], 1);
}

__global__ void scan_rowptr() {
    __shared__ int sums[256];
    __shared__ int offs[257];
    const int CH = (N_NODES + 255) / 256;
    int t = threadIdx.x;
    int base = t * CH;
    int s = 0;
    for (int i = 0; i < CH; i++) {
        int idx = base + i;
        if (idx < N_NODES) s += g_deg[idx];
    }
    sums[t] = s;
    __syncthreads();
    if (t == 0) {
        int acc = 0;
        for (int i = 0; i < 256; i++) { offs[i] = acc; acc += sums[i]; }
        offs[256] = acc;
    }
    __syncthreads();
    int run = offs[t];
    for (int i = 0; i < CH; i++) {
        int idx = base + i;
        if (idx < N_NODES) { g_rowptr[idx] = run; run += g_deg[idx]; }
    }
    if (t == 255) g_rowptr[N_NODES] = offs[256];
}

__global__ void scatter_csr(const int* __restrict__ ei) {
    int e = blockIdx.x * blockDim.x + threadIdx.x;
    if (e >= E_TOT) return;
    int s, d; edge_sd(ei, e, s, d);
    int pos = atomicAdd(&g_next[d], 1);
    g_csr[pos] = s;
}

// ---------------- BF16 tensor-core GEMM (R8 config, proven) -----------------
#define BM 128
#define BN 128
#define BK 32
#define TS 40
#define A_ELE (BM * TS)
#define STAGE_BYTES (2 * A_ELE * 2)   // 20480
#define NSTAGE 4

__global__ __launch_bounds__(256, 2) void bf16_gemm(const __nv_bfloat16* __restrict__ A,
                                                    const __nv_bfloat16* __restrict__ BT,
                                                    __nv_bfloat16* __restrict__ C,
                                                    int M, int N, int K) {
    extern __shared__ __nv_bfloat16 smem[];
    const int tid   = threadIdx.x;
    const int wid   = tid >> 5;
    const int lane  = tid & 31;
    const int g     = lane >> 2;
    const int t     = lane & 3;
    const int warpM = wid & 1;
    const int warpN = wid >> 1;
    const int rowBase = blockIdx.y * BM;
    const int colBase = blockIdx.x * BN;

    float acc[4][4][4];
    #pragma unroll
    for (int i = 0; i < 4; i++)
        #pragma unroll
        for (int j = 0; j < 4; j++)
            #pragma unroll
            for (int k = 0; k < 4; k++) acc[i][j][k] = 0.0f;

    uint32_t smemBase = (uint32_t)__cvta_generic_to_shared(smem);
    const int T = K / BK;

    const int laneRow  = lane & 15;
    const int laneHalf = lane >> 4;
    const uint32_t aOff = ((warpM * 64 + laneRow) * TS + laneHalf * 8) * 2;
    const uint32_t bOff = (uint32_t)A_ELE * 2 + ((warpN * 32 + laneRow) * TS + laneHalf * 8) * 2;

    auto load_tiles = [&](int it, int stage) {
        int k0 = it * BK;
        uint32_t sA = smemBase + stage * STAGE_BYTES;
        uint32_t sB = sA + A_ELE * 2;
        #pragma unroll
        for (int j = 0; j < 2; j++) {
            int idx = tid + j * 256;
            int m   = idx >> 2;
            int c8  = (idx & 3) * 8;
            int gr  = rowBase + m;
            const __nv_bfloat16* src = A + (size_t)(gr < M ? gr : 0) * K + k0 + c8;
            cpAsync16(sA + (m * TS + c8) * 2, src, (gr < M) ? 16 : 0);
        }
        #pragma unroll
        for (int j = 0; j < 2; j++) {
            int idx = tid + j * 256;
            int n   = idx >> 2;
            int c8  = (idx & 3) * 8;
            const __nv_bfloat16* src = BT + (size_t)(colBase + n) * K + k0 + c8;
            cpAsync16(sB + (n * TS + c8) * 2, src, 16);
        }
    };

    #pragma unroll
    for (int s = 0; s < 3; s++) {
        if (s < T) load_tiles(s, s);
        cpCommit();
    }

    for (int it = 0; it < T; ++it) {
        cpWait<2>();
        __syncthreads();
        if (it + 3 < T) load_tiles(it + 3, (it + 3) & (NSTAGE - 1));
        cpCommit();

        uint32_t sStage = smemBase + (it & (NSTAGE - 1)) * STAGE_BYTES;

        #pragma unroll
        for (int ks = 0; ks < 2; ks++) {
            uint32_t af[4][4], bf[4][2];
            #pragma unroll
            for (int mt = 0; mt < 4; mt++)
                ldsmX4(af[mt][0], af[mt][1], af[mt][2], af[mt][3],
                       sStage + aOff + (mt * 16 * TS + ks * 16) * 2);
            #pragma unroll
            for (int nt2 = 0; nt2 < 2; nt2++)
                ldsmX4(bf[2 * nt2][0], bf[2 * nt2 + 1][0], bf[2 * nt2][1], bf[2 * nt2 + 1][1],
                       sStage + bOff + (nt2 * 16 * TS + ks * 16) * 2);
            #pragma unroll
            for (int mt = 0; mt < 4; mt++)
                #pragma unroll
                for (int nt = 0; nt < 4; nt++) {
                    float* d = acc[mt][nt];
                    asm volatile(
                        "mma.sync.aligned.m16n8k16.row.col.f32.bf16.bf16.f32 "
                        "{%0,%1,%2,%3}, {%4,%5,%6,%7}, {%8,%9}, {%0,%1,%2,%3};"
                        : "+f"(d[0]), "+f"(d[1]), "+f"(d[2]), "+f"(d[3])
                        : "r"(af[mt][0]), "r"(af[mt][1]), "r"(af[mt][2]), "r"(af[mt][3]),
                          "r"(bf[nt][0]), "r"(bf[nt][1]));
                }
        }
    }

    #pragma unroll
    for (int mt = 0; mt < 4; mt++) {
        int r0 = rowBase + warpM * 64 + mt * 16 + g;
        #pragma unroll
        for (int nt = 0; nt < 4; nt++) {
            int c = colBase + warpN * 32 + nt * 8 + 2 * t;
            if (r0 < M)
                *(__nv_bfloat162*)&C[(size_t)r0 * N + c] =
                    __floats2bfloat162_rn(acc[mt][nt][0], acc[mt][nt][1]);
            if (r0 + 8 < M)
                *(__nv_bfloat162*)&C[(size_t)(r0 + 8) * N + c] =
                    __floats2bfloat162_rn(acc[mt][nt][2], acc[mt][nt][3]);
        }
    }
}

// ---------------- attention scores a_s/a_d (bf16 h, 2 heads/iter) ------------
__global__ void attn_scores(const __nv_bfloat16* __restrict__ h,
                            const float* __restrict__ att_s,
                            const float* __restrict__ att_d) {
    int n = blockIdx.x * (blockDim.x / 32) + (threadIdx.x >> 5);
    int lane = threadIdx.x & 31;
    if (n >= N_NODES) return;
    const __nv_bfloat16* hrow = h + (size_t)n * D1;
    int half = lane >> 4;          // which head of the pair
    int cp   = lane & 15;          // channel pair within head
    #pragma unroll 4
    for (int it = 0; it < HEADS / 2; it++) {
        int head = it * 2 + half;
        int c = head * 32 + 2 * cp;
        float2 f = __bfloat1622float2(*(const __nv_bfloat162*)&hrow[c]);
        float s = f.x * att_s[c] + f.y * att_s[c + 1];
        float d = f.x * att_d[c] + f.y * att_d[c + 1];
        #pragma unroll
        for (int o = 8; o; o >>= 1) {
            s += __shfl_down_sync(0xffffffffu, s, o, 16);
            d += __shfl_down_sync(0xffffffffu, d, o, 16);
        }
        if (cp == 0) {
            g_as[n * HEADS + head] = s;
            g_ad[n * HEADS + head] = d;
        }
    }
}

// ---------------- fused per-dst softmax + aggregate core (R11 proven) --------
struct AggSmem {
    float ad[HEADS];
    float den[HEADS];
    float alpha[2][HEADS];
    float lane_sum[OUTD];
};

__device__ __forceinline__ void fused_agg_core(const __nv_bfloat16* __restrict__ hbf,
                                               int dst, int t, AggSmem& sm, float acc[14]) {
    const int start = g_rowptr[dst];
    const int deg   = g_rowptr[dst + 1] - start;

    if (t < HEADS) {
        sm.ad[t]  = g_ad[dst * HEADS + t];
        sm.den[t] = 0.0f;
    }
    __syncthreads();

    // pass 1: denominator (no max shift; scores O(5), exp can't overflow fp32)
    for (int idx = t; idx < deg * HEADS; idx += 128) {
        int e = idx / HEADS, hd = idx - e * HEADS;
        int src = g_csr[start + e];
        float s = g_as[src * HEADS + hd] + sm.ad[hd];
        s = (s > 0.0f) ? s : 0.2f * s;
        atomicAdd(&sm.den[hd], expf(s));
    }
    __syncthreads();

    // pass 2: aggregate alpha * h[src]
    #pragma unroll
    for (int j = 0; j < 14; j++) acc[j] = 0.0f;
    for (int e = 0; e < deg; e++) {
        int p = e & 1;
        int src = g_csr[start + e];
        if (t < HEADS) {
            float s = g_as[src * HEADS + t] + sm.ad[t];
            s = (s > 0.0f) ? s : 0.2f * s;
            sm.alpha[p][t] = expf(s) / sm.den[t];
        }
        __syncthreads();
        const __nv_bfloat16* hs = hbf + (size_t)src * D1;
        #pragma unroll
        for (int j = 0; j < 7; j++) {
            int c = 2 * t + 256 * j;
            float a = sm.alpha[p][c >> 5];
            float2 f = __bfloat1622float2(*(const __nv_bfloat162*)&hs[c]);
            acc[2 * j]     += a * f.x;
            acc[2 * j + 1] += a * f.y;
        }
    }
}

// layer 1: fused agg + bias + ELU + BN1 -> bf16
__global__ __launch_bounds__(128) void gat_layer1(const __nv_bfloat16* __restrict__ hbf,
                                                  __nv_bfloat16* __restrict__ out,
                                                  const float* __restrict__ b,
                                                  const float* __restrict__ gam,
                                                  const float* __restrict__ bet,
                                                  const float* __restrict__ mu,
                                                  const float* __restrict__ var) {
    __shared__ AggSmem sm;
    int dst = blockIdx.x, t = threadIdx.x;
    float acc[14];
    fused_agg_core(hbf, dst, t, sm, acc);

    __nv_bfloat16* orow = out + (size_t)dst * D1;
    #pragma unroll
    for (int j = 0; j < 7; j++) {
        int c = 2 * t + 256 * j;
        float r[2];
        #pragma unroll
        for (int q = 0; q < 2; q++) {
            float xx = acc[2 * j + q] + b[c + q];
            xx = (xx > 0.0f) ? xx : (expf(xx) - 1.0f);
            r[q] = (xx - mu[c + q]) * rsqrtf(var[c + q] + EPS_BN) * gam[c + q] + bet[c + q];
        }
        *(__nv_bfloat162*)&orow[c] = __floats2bfloat162_rn(r[0], r[1]);
    }
}

// layer 2: fused agg + head-mean + bias + BN2 + pool
__global__ __launch_bounds__(128) void gat_layer2(const __nv_bfloat16* __restrict__ hbf,
                                                  const int* __restrict__ batch,
                                                  const float* __restrict__ b2,
                                                  const float* __restrict__ g2,
                                                  const float* __restrict__ bt2,
                                                  const float* __restrict__ mu2,
                                                  const float* __restrict__ var2) {
    __shared__ AggSmem sm;
    int dst = blockIdx.x, t = threadIdx.x;
    float acc[14];
    fused_agg_core(hbf, dst, t, sm, acc);

    if (t < OUTD) sm.lane_sum[t] = 0.0f;
    __syncthreads();
    #pragma unroll
    for (int j = 0; j < 7; j++) {
        int c = 2 * t + 256 * j;
        atomicAdd(&sm.lane_sum[c & 31], acc[2 * j]);
        atomicAdd(&sm.lane_sum[(c + 1) & 31], acc[2 * j + 1]);
    }
    __syncthreads();
    if (t < OUTD) {
        float s = sm.lane_sum[t] * (1.0f / HEADS) + b2[t];
        s = (s - mu2[t]) * rsqrtf(var2[t] + EPS_BN) * g2[t] + bt2[t];
        int gi = batch[dst];
        atomicAdd(&g_pool[gi * OUTD + t], s);
        if (t == 0) atomicAdd(&g_cnt[gi], 1.0f);
    }
}

// ---------------- final linear ----------------------------------------------
__global__ void final_lin(const float* __restrict__ lin_w,
                          const float* __restrict__ lin_b,
                          float* __restrict__ out) {
    int i = blockIdx.x * blockDim.x + threadIdx.x;
    if (i >= N_GRAPHS * N_CLASS) return;
    int g = i / N_CLASS, c = i - g * N_CLASS;
    float cnt = fmaxf(g_cnt[g], 1.0f);
    float acc = lin_b[c];
    #pragma unroll
    for (int k = 0; k < OUTD; k++)
        acc += (g_pool[g * OUTD + k] / cnt) * lin_w[k * N_CLASS + c];
    out[i] = acc;
}

// ---------------- host orchestration (R13 order, byte-exact) -----------------
extern "C" void kernel_launch(void* const* d_in, const int* in_sizes, int n_in,
                              void* d_out, int out_size) {
    const float* x        = (const float*)d_in[0];
    const int*   ei       = (const int*)  d_in[1];
    const int*   batch    = (const int*)  d_in[2];
    const float* W1       = (const float*)d_in[3];
    const float* att_src1 = (const float*)d_in[4];
    const float* att_dst1 = (const float*)d_in[5];
    const float* b1       = (const float*)d_in[6];
    const float* bn1_g    = (const float*)d_in[7];
    const float* bn1_b    = (const float*)d_in[8];
    const float* bn1_m    = (const float*)d_in[9];
    const float* bn1_v    = (const float*)d_in[10];
    const float* W2       = (const float*)d_in[11];
    const float* att_src2 = (const float*)d_in[12];
    const float* att_dst2 = (const float*)d_in[13];
    const float* b2       = (const float*)d_in[14];
    const float* bn2_g    = (const float*)d_in[15];
    const float* bn2_b    = (const float*)d_in[16];
    const float* bn2_m    = (const float*)d_in[17];
    const float* bn2_v    = (const float*)d_in[18];
    const float* lin_w    = (const float*)d_in[19];
    const float* lin_b    = (const float*)d_in[20];
    float* out = (float*)d_out;

    float *pool_ptr, *cnt_ptr;
    int *deg_ptr, *rowptr_ptr, *next_ptr;
    __nv_bfloat16 *xbf, *w1t, *w2t, *actbf, *hbf;
    cudaGetSymbolAddress((void**)&pool_ptr,  g_pool);
    cudaGetSymbolAddress((void**)&cnt_ptr,   g_cnt);
    cudaGetSymbolAddress((void**)&deg_ptr,   g_deg);
    cudaGetSymbolAddress((void**)&rowptr_ptr,g_rowptr);
    cudaGetSymbolAddress((void**)&next_ptr,  g_next);
    cudaGetSymbolAddress((void**)&xbf,       g_xbf);
    cudaGetSymbolAddress((void**)&w1t,       g_w1t);
    cudaGetSymbolAddress((void**)&w2t,       g_w2t);
    cudaGetSymbolAddress((void**)&actbf,     g_actbf);
    cudaGetSymbolAddress((void**)&hbf,       g_hbf);

    const int SMEM_BYTES = NSTAGE * STAGE_BYTES;   // 81920 B
    cudaFuncSetAttribute(bf16_gemm, cudaFuncAttributeMaxDynamicSharedMemorySize, SMEM_BYTES);
    dim3 gemmGrid(D1 / BN, (N_NODES + BM - 1) / BM);

    // ===== init + CSR build first, then conversions (R13 proven order) =====
    cudaMemsetAsync(deg_ptr, 0, (size_t)N_NODES * 4);
    cudaMemsetAsync(pool_ptr, 0, (size_t)N_GRAPHS * OUTD * 4);
    cudaMemsetAsync(cnt_ptr,  0, (size_t)N_GRAPHS * 4);
    count_deg<<<(E_TOT + 255) / 256, 256>>>(ei);                                   // 1
    scan_rowptr<<<1, 256>>>();                                                     // 2
    cudaMemcpyAsync(next_ptr, rowptr_ptr, (size_t)N_NODES * 4, cudaMemcpyDeviceToDevice);
    scatter_csr<<<(E_TOT + 255) / 256, 256>>>(ei);                                 // 3
    cvt_bf16<<<(N_NODES * N_FEAT / 4 + 255) / 256, 256>>>(x, xbf, N_NODES * N_FEAT / 4); // 4
    transpose_cvt<<<dim3(D1 / 32, N_FEAT / 32), dim3(32, 8)>>>(W1, w1t, N_FEAT, D1);     // 5

    // ===== layer 1 =====
    bf16_gemm<<<gemmGrid, 256, SMEM_BYTES>>>(xbf, w1t, hbf, N_NODES, D1, N_FEAT);  // 6
    transpose_cvt<<<dim3(D1 / 32, D1 / 32), dim3(32, 8)>>>(W2, w2t, D1, D1);       // 7 (for gemm2)
    attn_scores<<<(N_NODES + 7) / 8, 256>>>(hbf, att_src1, att_dst1);
    gat_layer1<<<N_NODES, 128>>>(hbf, actbf, b1, bn1_g, bn1_b, bn1_m, bn1_v);

    // ===== layer 2 =====
    bf16_gemm<<<gemmGrid, 256, SMEM_BYTES>>>(actbf, w2t, hbf, N_NODES, D1, D1);
    attn_scores<<<(N_NODES + 7) / 8, 256>>>(hbf, att_src2, att_dst2);
    gat_layer2<<<N_NODES, 128>>>(hbf, batch, b2, bn2_g, bn2_b, bn2_m, bn2_v);

    // ===== final linear =====
    final_lin<<<1, 128>>>(lin_w, lin_b, out);
}

// round 17
// speedup vs baseline: 1.0343x; 1.0343x over previous
#include <cuda_runtime.h>
#include <cuda_bf16.h>
#include <math.h>
#include <stdint.h>

#define N_NODES  20000
#define N_FEAT   128
#define HEADS    56
#define OUTD     32
#define D1       1792      // HEADS*OUTD
#define N_EDGES  100000
#define E_TOT    120000    // + self loops
#define N_GRAPHS 50
#define N_CLASS  2
#define EPS_BN   1e-5f

// ---------------- scratch (static device memory; no allocations) ------------
__device__ __nv_bfloat16 g_hbf [(size_t)N_NODES * D1];   // bf16 h (per layer)
__device__ __nv_bfloat16 g_actbf[(size_t)N_NODES * D1];  // bf16 activations
__device__ __nv_bfloat16 g_xbf [(size_t)N_NODES * N_FEAT];
__device__ __nv_bfloat16 g_w1t [(size_t)D1 * N_FEAT];    // W1^T [N][K]
__device__ __nv_bfloat16 g_w2t [(size_t)D1 * D1];        // W2^T [N][K]
__device__ float g_as[N_NODES * HEADS];
__device__ float g_ad[N_NODES * HEADS];
__device__ int   g_deg[N_NODES];
__device__ int   g_rowptr[N_NODES + 1];
__device__ int   g_next[N_NODES];
__device__ int   g_csr[E_TOT];          // src per CSR slot (by dst)
__device__ float g_pool[N_GRAPHS * OUTD];
__device__ float g_cnt[N_GRAPHS];

// ---------------- helpers ---------------------------------------------------
__device__ __forceinline__ void cpAsync16(uint32_t smem_addr, const void* gptr, int src_bytes) {
    asm volatile("cp.async.ca.shared.global [%0], [%1], 16, %2;"
                 :: "r"(smem_addr), "l"(gptr), "r"(src_bytes));
}
__device__ __forceinline__ void cpCommit() { asm volatile("cp.async.commit_group;"); }
template <int N>
__device__ __forceinline__ void cpWait() { asm volatile("cp.async.wait_group %0;" :: "n"(N)); }

__device__ __forceinline__ void ldsmX4(uint32_t& r0, uint32_t& r1, uint32_t& r2, uint32_t& r3,
                                       uint32_t addr) {
    asm volatile("ldmatrix.sync.aligned.m8n8.x4.shared.b16 {%0,%1,%2,%3}, [%4];"
                 : "=r"(r0), "=r"(r1), "=r"(r2), "=r"(r3) : "r"(addr));
}

__device__ __forceinline__ void edge_sd(const int* __restrict__ ei, int e, int& s, int& d) {
    if (e < N_EDGES) { s = ei[e]; d = ei[N_EDGES + e]; }
    else             { s = d = e - N_EDGES; }
}

// ---------------- f32 -> bf16 elementwise (vector of 4) ---------------------
__global__ void cvt_bf16(const float* __restrict__ in, __nv_bfloat16* __restrict__ out, int n4) {
    int i = blockIdx.x * blockDim.x + threadIdx.x;
    if (i >= n4) return;
    float4 v = ((const float4*)in)[i];
    ((__nv_bfloat162*)out)[2 * i]     = __floats2bfloat162_rn(v.x, v.y);
    ((__nv_bfloat162*)out)[2 * i + 1] = __floats2bfloat162_rn(v.z, v.w);
}

// ---------------- f32 [K][N] -> bf16 [N][K] tiled transpose -----------------
__global__ void transpose_cvt(const float* __restrict__ in, __nv_bfloat16* __restrict__ out,
                              int K, int N) {
    __shared__ float tile[32][33];
    int k0 = blockIdx.y * 32, n0 = blockIdx.x * 32;
    #pragma unroll
    for (int j = 0; j < 4; j++) {
        int kk = threadIdx.y + j * 8;
        tile[kk][threadIdx.x] = in[(size_t)(k0 + kk) * N + n0 + threadIdx.x];
    }
    __syncthreads();
    #pragma unroll
    for (int j = 0; j < 4; j++) {
        int nn = threadIdx.y + j * 8;
        out[(size_t)(n0 + nn) * K + k0 + threadIdx.x] = __float2bfloat16(tile[threadIdx.x][nn]);
    }
}

// ---------------- CSR build --------------------------------------------------
__global__ void count_deg(const int* __restrict__ ei) {
    int e = blockIdx.x * blockDim.x + threadIdx.x;
    if (e >= E_TOT) return;
    int s, d; edge_sd(ei, e, s, d);
    atomicAdd(&g_deg[d], 1);
}

__global__ void scan_rowptr() {
    __shared__ int sums[256];
    __shared__ int offs[257];
    const int CH = (N_NODES + 255) / 256;
    int t = threadIdx.x;
    int base = t * CH;
    int s = 0;
    for (int i = 0; i < CH; i++) {
        int idx = base + i;
        if (idx < N_NODES) s += g_deg[idx];
    }
    sums[t] = s;
    __syncthreads();
    if (t == 0) {
        int acc = 0;
        for (int i = 0; i < 256; i++) { offs[i] = acc; acc += sums[i]; }
        offs[256] = acc;
    }
    __syncthreads();
    int run = offs[t];
    for (int i = 0; i < CH; i++) {
        int idx = base + i;
        if (idx < N_NODES) { g_rowptr[idx] = run; run += g_deg[idx]; }
    }
    if (t == 255) g_rowptr[N_NODES] = offs[256];
}

__global__ void scatter_csr(const int* __restrict__ ei) {
    int e = blockIdx.x * blockDim.x + threadIdx.x;
    if (e >= E_TOT) return;
    int s, d; edge_sd(ei, e, s, d);
    int pos = atomicAdd(&g_next[d], 1);
    g_csr[pos] = s;
}

// ---------------- BF16 tensor-core GEMM (R8 config, proven) -----------------
#define BM 128
#define BN 128
#define BK 32
#define TS 40
#define A_ELE (BM * TS)
#define STAGE_BYTES (2 * A_ELE * 2)   // 20480
#define NSTAGE 4

__global__ __launch_bounds__(256, 2) void bf16_gemm(const __nv_bfloat16* __restrict__ A,
                                                    const __nv_bfloat16* __restrict__ BT,
                                                    __nv_bfloat16* __restrict__ C,
                                                    int M, int N, int K) {
    extern __shared__ __nv_bfloat16 smem[];
    const int tid   = threadIdx.x;
    const int wid   = tid >> 5;
    const int lane  = tid & 31;
    const int g     = lane >> 2;
    const int t     = lane & 3;
    const int warpM = wid & 1;
    const int warpN = wid >> 1;
    const int rowBase = blockIdx.y * BM;
    const int colBase = blockIdx.x * BN;

    float acc[4][4][4];
    #pragma unroll
    for (int i = 0; i < 4; i++)
        #pragma unroll
        for (int j = 0; j < 4; j++)
            #pragma unroll
            for (int k = 0; k < 4; k++) acc[i][j][k] = 0.0f;

    uint32_t smemBase = (uint32_t)__cvta_generic_to_shared(smem);
    const int T = K / BK;

    const int laneRow  = lane & 15;
    const int laneHalf = lane >> 4;
    const uint32_t aOff = ((warpM * 64 + laneRow) * TS + laneHalf * 8) * 2;
    const uint32_t bOff = (uint32_t)A_ELE * 2 + ((warpN * 32 + laneRow) * TS + laneHalf * 8) * 2;

    auto load_tiles = [&](int it, int stage) {
        int k0 = it * BK;
        uint32_t sA = smemBase + stage * STAGE_BYTES;
        uint32_t sB = sA + A_ELE * 2;
        #pragma unroll
        for (int j = 0; j < 2; j++) {
            int idx = tid + j * 256;
            int m   = idx >> 2;
            int c8  = (idx & 3) * 8;
            int gr  = rowBase + m;
            const __nv_bfloat16* src = A + (size_t)(gr < M ? gr : 0) * K + k0 + c8;
            cpAsync16(sA + (m * TS + c8) * 2, src, (gr < M) ? 16 : 0);
        }
        #pragma unroll
        for (int j = 0; j < 2; j++) {
            int idx = tid + j * 256;
            int n   = idx >> 2;
            int c8  = (idx & 3) * 8;
            const __nv_bfloat16* src = BT + (size_t)(colBase + n) * K + k0 + c8;
            cpAsync16(sB + (n * TS + c8) * 2, src, 16);
        }
    };

    #pragma unroll
    for (int s = 0; s < 3; s++) {
        if (s < T) load_tiles(s, s);
        cpCommit();
    }

    for (int it = 0; it < T; ++it) {
        cpWait<2>();
        __syncthreads();
        if (it + 3 < T) load_tiles(it + 3, (it + 3) & (NSTAGE - 1));
        cpCommit();

        uint32_t sStage = smemBase + (it & (NSTAGE - 1)) * STAGE_BYTES;

        #pragma unroll
        for (int ks = 0; ks < 2; ks++) {
            uint32_t af[4][4], bf[4][2];
            #pragma unroll
            for (int mt = 0; mt < 4; mt++)
                ldsmX4(af[mt][0], af[mt][1], af[mt][2], af[mt][3],
                       sStage + aOff + (mt * 16 * TS + ks * 16) * 2);
            #pragma unroll
            for (int nt2 = 0; nt2 < 2; nt2++)
                ldsmX4(bf[2 * nt2][0], bf[2 * nt2 + 1][0], bf[2 * nt2][1], bf[2 * nt2 + 1][1],
                       sStage + bOff + (nt2 * 16 * TS + ks * 16) * 2);
            #pragma unroll
            for (int mt = 0; mt < 4; mt++)
                #pragma unroll
                for (int nt = 0; nt < 4; nt++) {
                    float* d = acc[mt][nt];
                    asm volatile(
                        "mma.sync.aligned.m16n8k16.row.col.f32.bf16.bf16.f32 "
                        "{%0,%1,%2,%3}, {%4,%5,%6,%7}, {%8,%9}, {%0,%1,%2,%3};"
                        : "+f"(d[0]), "+f"(d[1]), "+f"(d[2]), "+f"(d[3])
                        : "r"(af[mt][0]), "r"(af[mt][1]), "r"(af[mt][2]), "r"(af[mt][3]),
                          "r"(bf[nt][0]), "r"(bf[nt][1]));
                }
        }
    }

    #pragma unroll
    for (int mt = 0; mt < 4; mt++) {
        int r0 = rowBase + warpM * 64 + mt * 16 + g;
        #pragma unroll
        for (int nt = 0; nt < 4; nt++) {
            int c = colBase + warpN * 32 + nt * 8 + 2 * t;
            if (r0 < M)
                *(__nv_bfloat162*)&C[(size_t)r0 * N + c] =
                    __floats2bfloat162_rn(acc[mt][nt][0], acc[mt][nt][1]);
            if (r0 + 8 < M)
                *(__nv_bfloat162*)&C[(size_t)(r0 + 8) * N + c] =
                    __floats2bfloat162_rn(acc[mt][nt][2], acc[mt][nt][3]);
        }
    }
}

// ---------------- attention scores a_s/a_d (bf16 h, 2 heads/iter) ------------
__global__ void attn_scores(const __nv_bfloat16* __restrict__ h,
                            const float* __restrict__ att_s,
                            const float* __restrict__ att_d) {
    int n = blockIdx.x * (blockDim.x / 32) + (threadIdx.x >> 5);
    int lane = threadIdx.x & 31;
    if (n >= N_NODES) return;
    const __nv_bfloat16* hrow = h + (size_t)n * D1;
    int half = lane >> 4;          // which head of the pair
    int cp   = lane & 15;          // channel pair within head
    #pragma unroll 4
    for (int it = 0; it < HEADS / 2; it++) {
        int head = it * 2 + half;
        int c = head * 32 + 2 * cp;
        float2 f = __bfloat1622float2(*(const __nv_bfloat162*)&hrow[c]);
        float s = f.x * att_s[c] + f.y * att_s[c + 1];
        float d = f.x * att_d[c] + f.y * att_d[c + 1];
        #pragma unroll
        for (int o = 8; o; o >>= 1) {
            s += __shfl_down_sync(0xffffffffu, s, o, 16);
            d += __shfl_down_sync(0xffffffffu, d, o, 16);
        }
        if (cp == 0) {
            g_as[n * HEADS + head] = s;
            g_ad[n * HEADS + head] = d;
        }
    }
}

// ---------------- fused per-dst softmax + aggregate core (R11 proven) --------
struct AggSmem {
    float ad[HEADS];
    float den[HEADS];
    float alpha[2][HEADS];
    float lane_sum[OUTD];
};

__device__ __forceinline__ void fused_agg_core(const __nv_bfloat16* __restrict__ hbf,
                                               int dst, int t, AggSmem& sm, float acc[14]) {
    const int start = g_rowptr[dst];
    const int deg   = g_rowptr[dst + 1] - start;

    if (t < HEADS) {
        sm.ad[t]  = g_ad[dst * HEADS + t];
        sm.den[t] = 0.0f;
    }
    __syncthreads();

    // pass 1: denominator (no max shift; scores O(5), exp can't overflow fp32)
    for (int idx = t; idx < deg * HEADS; idx += 128) {
        int e = idx / HEADS, hd = idx - e * HEADS;
        int src = g_csr[start + e];
        float s = g_as[src * HEADS + hd] + sm.ad[hd];
        s = (s > 0.0f) ? s : 0.2f * s;
        atomicAdd(&sm.den[hd], expf(s));
    }
    __syncthreads();

    // pass 2: aggregate alpha * h[src]
    #pragma unroll
    for (int j = 0; j < 14; j++) acc[j] = 0.0f;
    for (int e = 0; e < deg; e++) {
        int p = e & 1;
        int src = g_csr[start + e];
        if (t < HEADS) {
            float s = g_as[src * HEADS + t] + sm.ad[t];
            s = (s > 0.0f) ? s : 0.2f * s;
            sm.alpha[p][t] = expf(s) / sm.den[t];
        }
        __syncthreads();
        const __nv_bfloat16* hs = hbf + (size_t)src * D1;
        #pragma unroll
        for (int j = 0; j < 7; j++) {
            int c = 2 * t + 256 * j;
            float a = sm.alpha[p][c >> 5];
            float2 f = __bfloat1622float2(*(const __nv_bfloat162*)&hs[c]);
            acc[2 * j]     += a * f.x;
            acc[2 * j + 1] += a * f.y;
        }
    }
}

// layer 1: fused agg + bias + ELU + BN1 -> bf16
__global__ __launch_bounds__(128) void gat_layer1(const __nv_bfloat16* __restrict__ hbf,
                                                  __nv_bfloat16* __restrict__ out,
                                                  const float* __restrict__ b,
                                                  const float* __restrict__ gam,
                                                  const float* __restrict__ bet,
                                                  const float* __restrict__ mu,
                                                  const float* __restrict__ var) {
    __shared__ AggSmem sm;
    int dst = blockIdx.x, t = threadIdx.x;
    float acc[14];
    fused_agg_core(hbf, dst, t, sm, acc);

    __nv_bfloat16* orow = out + (size_t)dst * D1;
    #pragma unroll
    for (int j = 0; j < 7; j++) {
        int c = 2 * t + 256 * j;
        float r[2];
        #pragma unroll
        for (int q = 0; q < 2; q++) {
            float xx = acc[2 * j + q] + b[c + q];
            xx = (xx > 0.0f) ? xx : (expf(xx) - 1.0f);
            r[q] = (xx - mu[c + q]) * rsqrtf(var[c + q] + EPS_BN) * gam[c + q] + bet[c + q];
        }
        *(__nv_bfloat162*)&orow[c] = __floats2bfloat162_rn(r[0], r[1]);
    }
}

// layer 2: fused agg + head-mean + bias + BN2 + pool
__global__ __launch_bounds__(128) void gat_layer2(const __nv_bfloat16* __restrict__ hbf,
                                                  const int* __restrict__ batch,
                                                  const float* __restrict__ b2,
                                                  const float* __restrict__ g2,
                                                  const float* __restrict__ bt2,
                                                  const float* __restrict__ mu2,
                                                  const float* __restrict__ var2) {
    __shared__ AggSmem sm;
    int dst = blockIdx.x, t = threadIdx.x;
    float acc[14];
    fused_agg_core(hbf, dst, t, sm, acc);

    if (t < OUTD) sm.lane_sum[t] = 0.0f;
    __syncthreads();
    #pragma unroll
    for (int j = 0; j < 7; j++) {
        int c = 2 * t + 256 * j;
        atomicAdd(&sm.lane_sum[c & 31], acc[2 * j]);
        atomicAdd(&sm.lane_sum[(c + 1) & 31], acc[2 * j + 1]);
    }
    __syncthreads();
    if (t < OUTD) {
        float s = sm.lane_sum[t] * (1.0f / HEADS) + b2[t];
        s = (s - mu2[t]) * rsqrtf(var2[t] + EPS_BN) * g2[t] + bt2[t];
        int gi = batch[dst];
        atomicAdd(&g_pool[gi * OUTD + t], s);
        if (t == 0) atomicAdd(&g_cnt[gi], 1.0f);
    }
}

// ---------------- final linear ----------------------------------------------
__global__ void final_lin(const float* __restrict__ lin_w,
                          const float* __restrict__ lin_b,
                          float* __restrict__ out) {
    int i = blockIdx.x * blockDim.x + threadIdx.x;
    if (i >= N_GRAPHS * N_CLASS) return;
    int g = i / N_CLASS, c = i - g * N_CLASS;
    float cnt = fmaxf(g_cnt[g], 1.0f);
    float acc = lin_b[c];
    #pragma unroll
    for (int k = 0; k < OUTD; k++)
        acc += (g_pool[g * OUTD + k] / cnt) * lin_w[k * N_CLASS + c];
    out[i] = acc;
}

// ---------------- host orchestration (R13 order, byte-exact) -----------------
extern "C" void kernel_launch(void* const* d_in, const int* in_sizes, int n_in,
                              void* d_out, int out_size) {
    const float* x        = (const float*)d_in[0];
    const int*   ei       = (const int*)  d_in[1];
    const int*   batch    = (const int*)  d_in[2];
    const float* W1       = (const float*)d_in[3];
    const float* att_src1 = (const float*)d_in[4];
    const float* att_dst1 = (const float*)d_in[5];
    const float* b1       = (const float*)d_in[6];
    const float* bn1_g    = (const float*)d_in[7];
    const float* bn1_b    = (const float*)d_in[8];
    const float* bn1_m    = (const float*)d_in[9];
    const float* bn1_v    = (const float*)d_in[10];
    const float* W2       = (const float*)d_in[11];
    const float* att_src2 = (const float*)d_in[12];
    const float* att_dst2 = (const float*)d_in[13];
    const float* b2       = (const float*)d_in[14];
    const float* bn2_g    = (const float*)d_in[15];
    const float* bn2_b    = (const float*)d_in[16];
    const float* bn2_m    = (const float*)d_in[17];
    const float* bn2_v    = (const float*)d_in[18];
    const float* lin_w    = (const float*)d_in[19];
    const float* lin_b    = (const float*)d_in[20];
    float* out = (float*)d_out;

    float *pool_ptr, *cnt_ptr;
    int *deg_ptr, *rowptr_ptr, *next_ptr;
    __nv_bfloat16 *xbf, *w1t, *w2t, *actbf, *hbf;
    cudaGetSymbolAddress((void**)&pool_ptr,  g_pool);
    cudaGetSymbolAddress((void**)&cnt_ptr,   g_cnt);
    cudaGetSymbolAddress((void**)&deg_ptr,   g_deg);
    cudaGetSymbolAddress((void**)&rowptr_ptr,g_rowptr);
    cudaGetSymbolAddress((void**)&next_ptr,  g_next);
    cudaGetSymbolAddress((void**)&xbf,       g_xbf);
    cudaGetSymbolAddress((void**)&w1t,       g_w1t);
    cudaGetSymbolAddress((void**)&w2t,       g_w2t);
    cudaGetSymbolAddress((void**)&actbf,     g_actbf);
    cudaGetSymbolAddress((void**)&hbf,       g_hbf);

    const int SMEM_BYTES = NSTAGE * STAGE_BYTES;   // 81920 B
    cudaFuncSetAttribute(bf16_gemm, cudaFuncAttributeMaxDynamicSharedMemorySize, SMEM_BYTES);
    dim3 gemmGrid(D1 / BN, (N_NODES + BM - 1) / BM);

    // ===== init + CSR build first, then conversions (R13 proven order) =====
    cudaMemsetAsync(deg_ptr, 0, (size_t)N_NODES * 4);
    cudaMemsetAsync(pool_ptr, 0, (size_t)N_GRAPHS * OUTD * 4);
    cudaMemsetAsync(cnt_ptr,  0, (size_t)N_GRAPHS * 4);
    count_deg<<<(E_TOT + 255) / 256, 256>>>(ei);                                   // 1
    scan_rowptr<<<1, 256>>>();                                                     // 2
    cudaMemcpyAsync(next_ptr, rowptr_ptr, (size_t)N_NODES * 4, cudaMemcpyDeviceToDevice);
    scatter_csr<<<(E_TOT + 255) / 256, 256>>>(ei);                                 // 3
    cvt_bf16<<<(N_NODES * N_FEAT / 4 + 255) / 256, 256>>>(x, xbf, N_NODES * N_FEAT / 4); // 4
    transpose_cvt<<<dim3(D1 / 32, N_FEAT / 32), dim3(32, 8)>>>(W1, w1t, N_FEAT, D1);     // 5

    // ===== layer 1 =====
    bf16_gemm<<<gemmGrid, 256, SMEM_BYTES>>>(xbf, w1t, hbf, N_NODES, D1, N_FEAT);  // 6
    transpose_cvt<<<dim3(D1 / 32, D1 / 32), dim3(32, 8)>>>(W2, w2t, D1, D1);       // 7 (for gemm2)
    attn_scores<<<(N_NODES + 7) / 8, 256>>>(hbf, att_src1, att_dst1);
    gat_layer1<<<N_NODES, 128>>>(hbf, actbf, b1, bn1_g, bn1_b, bn1_m, bn1_v);

    // ===== layer 2 =====
    bf16_gemm<<<gemmGrid, 256, SMEM_BYTES>>>(actbf, w2t, hbf, N_NODES, D1, D1);
    attn_scores<<<(N_NODES + 7) / 8, 256>>>(hbf, att_src2, att_dst2);
    gat_layer2<<<N_NODES, 128>>>(hbf, batch, b2, bn2_g, bn2_b, bn2_m, bn2_v);

    // ===== final linear =====
    final_lin<<<1, 128>>>(lin_w, lin_b, out);
}